// round 6
// baseline (speedup 1.0000x reference)
#include <cuda_runtime.h>
#include <cuda_bf16.h>

// RoIPooling: crop_and_resize bilinear, POOL 7x7.
// feature_map: [B=8, H=64, W=64, C=256] fp32
// roi_bboxes:  [B=8, N=1000, 4] fp32 (y1,x1,y2,x2) normalized
// out:         [B, N, 7, 7, C] fp32
//
// R6: R3 skeleton (one warp per (box,py,channel-half), 4-corner LDG.128
// batch per px) with the px loop FULLY UNROLLED and a 42-reg budget
// (launch_bounds 256,6). ptxas software-pipelines across px iterations:
// next px's address math + loads issue under current px's FFMA chain,
// raising effective MLP beyond 4 without the hand-pairing that failed in R4.

namespace {

constexpr int Hc = 64;
constexpr int Wc = 64;
constexpr int Cc = 256;          // channels
constexpr int CQ = Cc / 4;       // 64 float4 per pixel
constexpr int PH = 7;
constexpr int PW = 7;
constexpr int Bc = 8;
constexpr int Nc = 1000;
constexpr int NUM_WARPS = Bc * Nc * PH * 2;     // 112000 (2 channel-halves)
constexpr int WARPS_PER_BLOCK = 8;
constexpr int THREADS = WARPS_PER_BLOCK * 32;

__global__ __launch_bounds__(THREADS, 6) void roi_pool_kernel(
    const float* __restrict__ fm,
    const float* __restrict__ boxes,
    float* __restrict__ out)
{
    const int gwarp = (blockIdx.x * WARPS_PER_BLOCK) + (threadIdx.x >> 5);
    const int lane = threadIdx.x & 31;

    // gwarp = (box * PH + py) * 2 + half   (grid is exact: no bounds guard)
    const int half = gwarp & 1;
    const int row  = gwarp >> 1;       // box * PH + py
    const int py   = row % PH;
    const int box  = row / PH;         // 0 .. B*N-1 (batch-major, matches output)
    const int b    = box / Nc;

    // Box coords (16B aligned)
    const float4 bc = __ldg(reinterpret_cast<const float4*>(boxes) + box);
    const float by1 = bc.x, bx1 = bc.y, by2 = bc.z, bx2 = bc.w;

    const float hm1 = (float)(Hc - 1);
    const float wm1 = (float)(Wc - 1);

    // ---- y math: once per warp (matches reference op order) ----
    const float y = by1 * hm1 + (float)py * ((by2 - by1) * hm1 / (float)(PH - 1));
    const float y0f = floorf(y);
    const float wy  = y - y0f;
    int y0 = (int)y0f;  y0 = min(max(y0, 0), Hc - 1);
    const int y1i = min(y0 + 1, Hc - 1);
    const bool valid_y = (y >= 0.0f) & (y <= hm1);

    // quad index within the pixel handled by this lane
    const int q = half * 32 + lane;

    // 32-bit float4 offsets (fm = 8.4M float4, out = 100.4M float4, both < 2^31)
    const float4* fm4 = reinterpret_cast<const float4*>(fm);
    const int bbase   = b * (Hc * Wc * CQ);
    const int rowT    = bbase + y0  * (Wc * CQ) + q;   // top row, this lane's quad
    const int rowB    = bbase + y1i * (Wc * CQ) + q;   // bottom row

    // ---- x constants: once per warp ----
    const float xbase = bx1 * wm1;
    const float dx    = (bx2 - bx1) * wm1 / (float)(PW - 1);

    unsigned int oofs = (unsigned int)row * (PW * CQ) + q;
    float4* o4 = reinterpret_cast<float4*>(out);

    #pragma unroll
    for (int px = 0; px < PW; ++px) {
        const float x   = xbase + (float)px * dx;   // same op order as reference
        const float x0f = floorf(x);
        const float wx  = x - x0f;
        int x0 = (int)x0f;  x0 = min(max(x0, 0), Wc - 1);
        const int x1i = min(x0 + 1, Wc - 1);
        // exact 0/1 multiplicative mask (r*1.0f == r for all finite r here)
        const float m = (valid_y & (x >= 0.0f) & (x <= wm1)) ? 1.0f : 0.0f;

        const int x0q = x0  * CQ;
        const int x1q = x1i * CQ;

        // 4 independent corner loads; unrolled loop lets ptxas overlap the
        // next px's loads with this px's FFMA chain.
        const float4 a = __ldg(fm4 + rowT + x0q);
        const float4 bq= __ldg(fm4 + rowT + x1q);
        const float4 c = __ldg(fm4 + rowB + x0q);
        const float4 d = __ldg(fm4 + rowB + x1q);

        float4 r;
        {
            float top, bot;
            top = a.x + (bq.x - a.x) * wx;  bot = c.x + (d.x - c.x) * wx;
            r.x = (top + (bot - top) * wy) * m;
            top = a.y + (bq.y - a.y) * wx;  bot = c.y + (d.y - c.y) * wx;
            r.y = (top + (bot - top) * wy) * m;
            top = a.z + (bq.z - a.z) * wx;  bot = c.z + (d.z - c.z) * wx;
            r.z = (top + (bot - top) * wy) * m;
            top = a.w + (bq.w - a.w) * wx;  bot = c.w + (d.w - c.w) * wx;
            r.w = (top + (bot - top) * wy) * m;
        }

        // Streaming store: keep the 401MB output stream from evicting the
        // 33.5MB feature map out of L2 (gathers depend on L2 hits).
        __stcs(o4 + oofs + px * CQ, r);
    }
}

} // namespace

extern "C" void kernel_launch(void* const* d_in, const int* in_sizes, int n_in,
                              void* d_out, int out_size) {
    const float* fm    = (const float*)d_in[0];
    const float* boxes = (const float*)d_in[1];
    float* out         = (float*)d_out;

    const int blocks = NUM_WARPS / WARPS_PER_BLOCK;  // 14000, exact
    roi_pool_kernel<<<blocks, THREADS>>>(fm, boxes, out);
}

// round 7
// speedup vs baseline: 1.0785x; 1.0785x over previous
#include <cuda_runtime.h>
#include <cuda_bf16.h>

// RoIPooling: crop_and_resize bilinear, POOL 7x7.
// feature_map: [B=8, H=64, W=64, C=256] fp32
// roi_bboxes:  [B=8, N=1000, 4] fp32 (y1,x1,y2,x2) normalized
// out:         [B, N, 7, 7, C] fp32
//
// R7: R3 skeleton (one warp per (box,py,channel-half), 4-corner LDG.128
// batch, 32 regs, 8 CTAs/SM) + WEIGHT-FORM bilinear: 4 corner weights
// computed once per px (warp-uniform), validity mask folded into weights.
// Per-quad math drops 28 -> 16 FFMA, shortening the issue phase between
// load batches. Exact-zero behavior preserved (all-zero weights -> r=0).

namespace {

constexpr int Hc = 64;
constexpr int Wc = 64;
constexpr int Cc = 256;          // channels
constexpr int CQ = Cc / 4;       // 64 float4 per pixel
constexpr int PH = 7;
constexpr int PW = 7;
constexpr int Bc = 8;
constexpr int Nc = 1000;
constexpr int NUM_WARPS = Bc * Nc * PH * 2;     // 112000 (2 channel-halves)
constexpr int WARPS_PER_BLOCK = 8;
constexpr int THREADS = WARPS_PER_BLOCK * 32;

__global__ __launch_bounds__(THREADS, 8) void roi_pool_kernel(
    const float* __restrict__ fm,
    const float* __restrict__ boxes,
    float* __restrict__ out)
{
    const int gwarp = (blockIdx.x * WARPS_PER_BLOCK) + (threadIdx.x >> 5);
    const int lane = threadIdx.x & 31;

    // gwarp = (box * PH + py) * 2 + half   (grid is exact: no bounds guard)
    const int half = gwarp & 1;
    const int row  = gwarp >> 1;       // box * PH + py
    const int py   = row % PH;
    const int box  = row / PH;         // 0 .. B*N-1 (batch-major, matches output)
    const int b    = box / Nc;

    // Box coords (16B aligned)
    const float4 bc = __ldg(reinterpret_cast<const float4*>(boxes) + box);
    const float by1 = bc.x, bx1 = bc.y, by2 = bc.z, bx2 = bc.w;

    const float hm1 = (float)(Hc - 1);
    const float wm1 = (float)(Wc - 1);

    // ---- y math: once per warp (matches reference op order) ----
    const float y = by1 * hm1 + (float)py * ((by2 - by1) * hm1 / (float)(PH - 1));
    const float y0f = floorf(y);
    const float wy  = y - y0f;
    int y0 = (int)y0f;  y0 = min(max(y0, 0), Hc - 1);
    const int y1i = min(y0 + 1, Hc - 1);
    const bool valid_y = (y >= 0.0f) & (y <= hm1);
    const float omwy = 1.0f - wy;

    // quad index within the pixel handled by this lane
    const int q = half * 32 + lane;

    // 32-bit float4 offsets (fm = 8.4M float4, out = 100.4M float4, both < 2^31)
    const float4* fm4 = reinterpret_cast<const float4*>(fm);
    const int bbase   = b * (Hc * Wc * CQ);
    const int rowT    = bbase + y0  * (Wc * CQ) + q;   // top row, this lane's quad
    const int rowB    = bbase + y1i * (Wc * CQ) + q;   // bottom row

    // ---- x constants: once per warp ----
    const float xbase = bx1 * wm1;
    const float dx    = (bx2 - bx1) * wm1 / (float)(PW - 1);

    unsigned int oofs = (unsigned int)row * (PW * CQ) + q;
    float4* o4 = reinterpret_cast<float4*>(out);

    #pragma unroll 1
    for (int px = 0; px < PW; ++px) {
        const float x   = xbase + (float)px * dx;   // same op order as reference
        const float x0f = floorf(x);
        const float wx  = x - x0f;
        int x0 = (int)x0f;  x0 = min(max(x0, 0), Wc - 1);
        const int x1i = min(x0 + 1, Wc - 1);
        const float m = (valid_y & (x >= 0.0f) & (x <= wm1)) ? 1.0f : 0.0f;

        // Corner weights (warp-uniform per px), mask folded in.
        // m==0 -> all weights 0 -> r == 0 exactly.
        const float omwx = 1.0f - wx;
        const float w00 = omwx * omwy * m;   // a: (y0, x0)
        const float w01 = wx   * omwy * m;   // b: (y0, x1)
        const float w10 = omwx * wy   * m;   // c: (y1, x0)
        const float w11 = wx   * wy   * m;   // d: (y1, x1)

        const int x0q = x0  * CQ;
        const int x1q = x1i * CQ;

        // Front-batch the 4 corner loads (MLP = 4, ~14 warps/SMSP resident)
        const float4 a = __ldg(fm4 + rowT + x0q);
        const float4 bq= __ldg(fm4 + rowT + x1q);
        const float4 c = __ldg(fm4 + rowB + x0q);
        const float4 d = __ldg(fm4 + rowB + x1q);

        float4 r;
        r.x = fmaf(a.x, w00, fmaf(bq.x, w01, fmaf(c.x, w10, d.x * w11)));
        r.y = fmaf(a.y, w00, fmaf(bq.y, w01, fmaf(c.y, w10, d.y * w11)));
        r.z = fmaf(a.z, w00, fmaf(bq.z, w01, fmaf(c.z, w10, d.z * w11)));
        r.w = fmaf(a.w, w00, fmaf(bq.w, w01, fmaf(c.w, w10, d.w * w11)));

        // Streaming store: keep the 401MB output stream from evicting the
        // 33.5MB feature map out of L2 (gathers depend on L2 hits).
        __stcs(o4 + oofs, r);
        oofs += CQ;
    }
}

} // namespace

extern "C" void kernel_launch(void* const* d_in, const int* in_sizes, int n_in,
                              void* d_out, int out_size) {
    const float* fm    = (const float*)d_in[0];
    const float* boxes = (const float*)d_in[1];
    float* out         = (float*)d_out;

    const int blocks = NUM_WARPS / WARPS_PER_BLOCK;  // 14000, exact
    roi_pool_kernel<<<blocks, THREADS>>>(fm, boxes, out);
}